// round 10
// baseline (speedup 1.0000x reference)
#include <cuda_runtime.h>
#include <math.h>

#define N_TOK 4096
#define D_DIM 2048
#define N_EXP 8
#define TOPK  2
#define CAP   512
#define PITCH 2052   // padded smem row (floats); row base stays 16B-aligned
#define BLK1  256
#define GRID1 128    // 128 blk * 8 warps * 4 tok = 4096

// Scratch (static device globals — no allocation)
__device__ int g_choice[N_TOK * TOPK];
__device__ int g_slot[N_TOK * TOPK];

__device__ __forceinline__ unsigned long long fma2(
        unsigned long long a, unsigned long long b, unsigned long long c) {
    unsigned long long d;
    asm("fma.rn.f32x2 %0, %1, %2, %3;" : "=l"(d) : "l"(a), "l"(b), "l"(c));
    return d;
}

// ---------------------------------------------------------------------------
// Kernel 1: logits = x @ W, top-2, softmax. 4 tokens per warp, packed f32x2
// FMA (halves FFMA issue), full W staged transposed in smem (one LDS.128
// feeds 64 MACs). 128 blocks x 256 threads.
// ---------------------------------------------------------------------------
__global__ __launch_bounds__(BLK1) void k_logits_topk(
        const float* __restrict__ x,
        const float* __restrict__ W,
        float* __restrict__ out) {
    __shared__ float wt[N_EXP * PITCH];   // 65.7 KB

    int tid  = threadIdx.x;
    int lane = tid & 31;
    int wrp  = tid >> 5;
    int t0   = (blockIdx.x * 8 + wrp) * 4;   // first of 4 tokens

    // stage ALL of W transposed: wt[e][d]
    for (int idx = tid; idx < D_DIM * N_EXP; idx += BLK1) {
        int d = idx >> 3;
        int e = idx & 7;
        wt[e * PITCH + d] = W[idx];
    }
    __syncthreads();

    // x rows as packed 16B chunks: .x={f0,f1} .y={f2,f3} (b64 f32x2 pairs)
    const ulonglong2* xr0 = reinterpret_cast<const ulonglong2*>(x) + (size_t)(t0 + 0) * (D_DIM / 4);
    const ulonglong2* xr1 = reinterpret_cast<const ulonglong2*>(x) + (size_t)(t0 + 1) * (D_DIM / 4);
    const ulonglong2* xr2 = reinterpret_cast<const ulonglong2*>(x) + (size_t)(t0 + 2) * (D_DIM / 4);
    const ulonglong2* xr3 = reinterpret_cast<const ulonglong2*>(x) + (size_t)(t0 + 3) * (D_DIM / 4);

    unsigned long long acc[4][N_EXP] = {};   // each is a packed f32x2 partial

    ulonglong2 xv[2][4];
    // preload u=0
    xv[0][0] = xr0[lane]; xv[0][1] = xr1[lane];
    xv[0][2] = xr2[lane]; xv[0][3] = xr3[lane];

    #pragma unroll
    for (int u = 0; u < 16; u++) {
        int nu = u + 1;
        if (nu < 16) {
            int jn = nu * 32 + lane;
            xv[nu & 1][0] = xr0[jn]; xv[nu & 1][1] = xr1[jn];
            xv[nu & 1][2] = xr2[jn]; xv[nu & 1][3] = xr3[jn];
        }
        int j = u * 32 + lane;                // float4 index in [0,512)
        const ulonglong2* cur = xv[u & 1];
        #pragma unroll
        for (int e = 0; e < N_EXP; e++) {
            ulonglong2 w = *reinterpret_cast<const ulonglong2*>(&wt[e * PITCH + j * 4]);
            #pragma unroll
            for (int t = 0; t < 4; t++) {
                acc[t][e] = fma2(cur[t].x, w.x, acc[t][e]);
                acc[t][e] = fma2(cur[t].y, w.y, acc[t][e]);
            }
        }
    }

    // horizontal add of each f32x2 pair, then warp butterfly reduce
    float logit[4][N_EXP];
    #pragma unroll
    for (int t = 0; t < 4; t++) {
        #pragma unroll
        for (int e = 0; e < N_EXP; e++) {
            unsigned int lo_u = (unsigned int)(acc[t][e] & 0xffffffffull);
            unsigned int hi_u = (unsigned int)(acc[t][e] >> 32);
            float s = __uint_as_float(lo_u) + __uint_as_float(hi_u);
            #pragma unroll
            for (int off = 16; off > 0; off >>= 1)
                s += __shfl_xor_sync(0xffffffffu, s, off);
            logit[t][e] = s;
        }
    }

    if (lane == 0) {
        float* gate = out + (size_t)N_TOK * N_EXP * CAP;
        float* idxf = gate + N_TOK * TOPK;
        #pragma unroll
        for (int t = 0; t < 4; t++) {
            int tok = t0 + t;
            float best = -INFINITY, sec = -INFINITY;
            int bi = 0, si = 0;
            #pragma unroll
            for (int e = 0; e < N_EXP; e++) {
                float v = logit[t][e];
                if (v > best)     { sec = best; si = bi; best = v; bi = e; }
                else if (v > sec) { sec = v;    si = e; }
            }
            float g0 = 1.0f / (1.0f + expf(sec - best));
            gate[tok * 2 + 0] = g0;
            gate[tok * 2 + 1] = 1.0f - g0;
            idxf[tok * 2 + 0] = (float)bi;
            idxf[tok * 2 + 1] = (float)si;
            g_choice[tok * 2 + 0] = bi;
            g_choice[tok * 2 + 1] = si;
        }
    }
}

// ---------------------------------------------------------------------------
// Kernel 2: per-(k,expert) running-count prefix scan over 4096 tokens.
// 16 blocks (one per (k,e)), 1024 threads, 4 tokens/thread. (R2-proven)
// ---------------------------------------------------------------------------
__global__ void k_scan() {
    int k = blockIdx.x >> 3;
    int e = blockIdx.x & 7;
    int tid  = threadIdx.x;
    int lane = tid & 31;
    int wid  = tid >> 5;

    __shared__ int warp_sums[32];

    int n0 = tid * 4;
    int flags[4];
    int localex[4];
    int s = 0;
    #pragma unroll
    for (int j = 0; j < 4; j++) {
        flags[j]   = (g_choice[(n0 + j) * 2 + k] == e) ? 1 : 0;
        localex[j] = s;
        s += flags[j];
    }

    int inc = s;
    #pragma unroll
    for (int off = 1; off < 32; off <<= 1) {
        int v = __shfl_up_sync(0xffffffffu, inc, off);
        if (lane >= off) inc += v;
    }
    if (lane == 31) warp_sums[wid] = inc;
    __syncthreads();

    if (wid == 0) {
        int v = warp_sums[lane];
        int winc = v;
        #pragma unroll
        for (int off = 1; off < 32; off <<= 1) {
            int u = __shfl_up_sync(0xffffffffu, winc, off);
            if (lane >= off) winc += u;
        }
        warp_sums[lane] = winc - v;
    }
    __syncthreads();

    int thread_prefix = warp_sums[wid] + (inc - s);

    #pragma unroll
    for (int j = 0; j < 4; j++) {
        if (flags[j]) {
            int pri = thread_prefix + localex[j] + 1;
            g_slot[(n0 + j) * 2 + k] = (pri <= CAP) ? (pri - 1) : -1;
        }
    }
}

// ---------------------------------------------------------------------------
// Kernel 3 (fused zero+scatter): one block per token row (8*512 floats).
// Pure coalesced plain stores. (R2-proven, ~7.4 TB/s)
// ---------------------------------------------------------------------------
__global__ __launch_bounds__(256) void k_fill(float4* __restrict__ out) {
    int n   = blockIdx.x;
    int tid = threadIdx.x;

    int c0 = g_choice[n * 2 + 0];
    int c1 = g_choice[n * 2 + 1];
    int s0 = g_slot[n * 2 + 0];
    int s1 = g_slot[n * 2 + 1];
    int o0 = (s0 >= 0) ? c0 * CAP + s0 : -1;   // float index within row
    int o1 = (s1 >= 0) ? c1 * CAP + s1 : -1;

    float4* row = out + (size_t)n * (N_EXP * CAP / 4);

    #pragma unroll
    for (int q = 0; q < 4; q++) {
        int g = q * 256 + tid;         // float4 index within row [0,1024)
        int f = g * 4;                 // first float index
        float4 v;
        v.x = (o0 == f     || o1 == f    ) ? 1.0f : 0.0f;
        v.y = (o0 == f + 1 || o1 == f + 1) ? 1.0f : 0.0f;
        v.z = (o0 == f + 2 || o1 == f + 2) ? 1.0f : 0.0f;
        v.w = (o0 == f + 3 || o1 == f + 3) ? 1.0f : 0.0f;
        row[g] = v;
    }
}

// ---------------------------------------------------------------------------
extern "C" void kernel_launch(void* const* d_in, const int* in_sizes, int n_in,
                              void* d_out, int out_size) {
    const float* x = (const float*)d_in[0];   // [4096, 2048]
    const float* W = (const float*)d_in[1];   // [2048, 8]
    float* out = (float*)d_out;

    k_logits_topk<<<GRID1, BLK1>>>(x, W, out);
    k_scan<<<16, 1024>>>();
    k_fill<<<N_TOK, 256>>>((float4*)out);
}

// round 11
// speedup vs baseline: 1.0165x; 1.0165x over previous
#include <cuda_runtime.h>
#include <math.h>

#define N_TOK 4096
#define D_DIM 2048
#define N_EXP 8
#define TOPK  2
#define CAP   512
#define PITCH 2052                 // padded W smem row (floats)
#define BLK1  256
#define GRID1 128
#define TOK_BLK 32                 // tokens per block (8 warps * 4)
#define NSTAGES 4
#define CHUNK_F4 32                // 128 floats of D per token per chunk
#define STAGE_F4 (TOK_BLK * CHUNK_F4)          // 1024 float4 = 16 KB
#define NCHUNK (D_DIM / (CHUNK_F4 * 4))        // 16
#define DYN_SMEM (NSTAGES * STAGE_F4 * 16 + N_EXP * PITCH * 4)  // 131,200 B

// Scratch (static device globals — no allocation)
__device__ int g_choice[N_TOK * TOPK];
__device__ int g_slot[N_TOK * TOPK];

__device__ __forceinline__ unsigned long long fma2(
        unsigned long long a, unsigned long long b, unsigned long long c) {
    unsigned long long d;
    asm("fma.rn.f32x2 %0, %1, %2, %3;" : "=l"(d) : "l"(a), "l"(b), "l"(c));
    return d;
}

__device__ __forceinline__ void cp_async16(void* smem_dst, const void* gmem_src) {
    unsigned int dst = (unsigned int)__cvta_generic_to_shared(smem_dst);
    asm volatile("cp.async.cg.shared.global [%0], [%1], 16;\n"
                 :: "r"(dst), "l"(gmem_src));
}

// ---------------------------------------------------------------------------
// Kernel 1: logits = x @ W, top-2, softmax.
// x streamed via 4-deep cp.async smem pipeline (MLP lives in smem, not regs).
// Full W transposed in smem. 4 tokens/warp, packed f32x2 FMA.
// ---------------------------------------------------------------------------
__global__ __launch_bounds__(BLK1) void k_logits_topk(
        const float* __restrict__ x,
        const float* __restrict__ W,
        float* __restrict__ out) {
    extern __shared__ char smem_raw[];
    float4* xs = reinterpret_cast<float4*>(smem_raw);                 // ring: NSTAGES*1024 f4
    float*  wt = reinterpret_cast<float*>(smem_raw + NSTAGES * STAGE_F4 * 16);

    int tid  = threadIdx.x;
    int lane = tid & 31;
    int wrp  = tid >> 5;
    int tok_base = blockIdx.x * TOK_BLK;
    int tw0  = wrp * 4;                        // first of this warp's 4 tokens

    const float4* x4 = reinterpret_cast<const float4*>(x);

    // stage ALL of W transposed: wt[e][d]
    for (int idx = tid; idx < D_DIM * N_EXP; idx += BLK1) {
        int d = idx >> 3;
        int e = idx & 7;
        wt[e * PITCH + d] = W[idx];
    }

    // ---- prologue: fill pipeline stages 0..NSTAGES-1 ----
    #pragma unroll
    for (int s = 0; s < NSTAGES; s++) {
        #pragma unroll
        for (int o = 0; o < 4; o++) {
            int lin = o * BLK1 + tid;          // 0..1023
            int tw  = lin >> 5;
            int f   = lin & 31;
            cp_async16(&xs[s * STAGE_F4 + lin],
                       &x4[(size_t)(tok_base + tw) * (D_DIM / 4) + s * CHUNK_F4 + f]);
        }
        asm volatile("cp.async.commit_group;\n" ::: "memory");
    }

    unsigned long long acc[4][N_EXP] = {};     // packed f32x2 partials

    for (int c = 0; c < NCHUNK; c++) {
        asm volatile("cp.async.wait_group %0;\n" :: "n"(NSTAGES - 1) : "memory");
        __syncthreads();

        int slot = c & (NSTAGES - 1);
        const ulonglong2* xsl = reinterpret_cast<const ulonglong2*>(xs + slot * STAGE_F4);
        ulonglong2 xv[4];
        #pragma unroll
        for (int t = 0; t < 4; t++)
            xv[t] = xsl[(tw0 + t) * CHUNK_F4 + lane];

        int dbase = c * 128 + lane * 4;
        #pragma unroll
        for (int e = 0; e < N_EXP; e++) {
            ulonglong2 w = *reinterpret_cast<const ulonglong2*>(&wt[e * PITCH + dbase]);
            #pragma unroll
            for (int t = 0; t < 4; t++) {
                acc[t][e] = fma2(xv[t].x, w.x, acc[t][e]);
                acc[t][e] = fma2(xv[t].y, w.y, acc[t][e]);
            }
        }
        __syncthreads();                       // all warps done reading slot

        int nc = c + NSTAGES;
        if (nc < NCHUNK) {
            #pragma unroll
            for (int o = 0; o < 4; o++) {
                int lin = o * BLK1 + tid;
                int tw  = lin >> 5;
                int f   = lin & 31;
                cp_async16(&xs[slot * STAGE_F4 + lin],
                           &x4[(size_t)(tok_base + tw) * (D_DIM / 4) + nc * CHUNK_F4 + f]);
            }
        }
        asm volatile("cp.async.commit_group;\n" ::: "memory");  // keep group count aligned
    }

    // horizontal add of f32x2 pairs + warp butterfly reduce
    float logit[4][N_EXP];
    #pragma unroll
    for (int t = 0; t < 4; t++) {
        #pragma unroll
        for (int e = 0; e < N_EXP; e++) {
            float s = __uint_as_float((unsigned int)(acc[t][e] & 0xffffffffull)) +
                      __uint_as_float((unsigned int)(acc[t][e] >> 32));
            #pragma unroll
            for (int off = 16; off > 0; off >>= 1)
                s += __shfl_xor_sync(0xffffffffu, s, off);
            logit[t][e] = s;
        }
    }

    if (lane == 0) {
        float* gate = out + (size_t)N_TOK * N_EXP * CAP;
        float* idxf = gate + N_TOK * TOPK;
        #pragma unroll
        for (int t = 0; t < 4; t++) {
            int tok = tok_base + tw0 + t;
            float best = -INFINITY, sec = -INFINITY;
            int bi = 0, si = 0;
            #pragma unroll
            for (int e = 0; e < N_EXP; e++) {
                float v = logit[t][e];
                if (v > best)     { sec = best; si = bi; best = v; bi = e; }
                else if (v > sec) { sec = v;    si = e; }
            }
            float g0 = 1.0f / (1.0f + expf(sec - best));
            gate[tok * 2 + 0] = g0;
            gate[tok * 2 + 1] = 1.0f - g0;
            idxf[tok * 2 + 0] = (float)bi;
            idxf[tok * 2 + 1] = (float)si;
            g_choice[tok * 2 + 0] = bi;
            g_choice[tok * 2 + 1] = si;
        }
    }
}

// ---------------------------------------------------------------------------
// Kernel 2: per-(k,expert) running-count prefix scan. (R2-proven)
// ---------------------------------------------------------------------------
__global__ void k_scan() {
    int k = blockIdx.x >> 3;
    int e = blockIdx.x & 7;
    int tid  = threadIdx.x;
    int lane = tid & 31;
    int wid  = tid >> 5;

    __shared__ int warp_sums[32];

    int n0 = tid * 4;
    int flags[4];
    int localex[4];
    int s = 0;
    #pragma unroll
    for (int j = 0; j < 4; j++) {
        flags[j]   = (g_choice[(n0 + j) * 2 + k] == e) ? 1 : 0;
        localex[j] = s;
        s += flags[j];
    }

    int inc = s;
    #pragma unroll
    for (int off = 1; off < 32; off <<= 1) {
        int v = __shfl_up_sync(0xffffffffu, inc, off);
        if (lane >= off) inc += v;
    }
    if (lane == 31) warp_sums[wid] = inc;
    __syncthreads();

    if (wid == 0) {
        int v = warp_sums[lane];
        int winc = v;
        #pragma unroll
        for (int off = 1; off < 32; off <<= 1) {
            int u = __shfl_up_sync(0xffffffffu, winc, off);
            if (lane >= off) winc += u;
        }
        warp_sums[lane] = winc - v;
    }
    __syncthreads();

    int thread_prefix = warp_sums[wid] + (inc - s);

    #pragma unroll
    for (int j = 0; j < 4; j++) {
        if (flags[j]) {
            int pri = thread_prefix + localex[j] + 1;
            g_slot[(n0 + j) * 2 + k] = (pri <= CAP) ? (pri - 1) : -1;
        }
    }
}

// ---------------------------------------------------------------------------
// Kernel 3 (fused zero+scatter): one block per token row. (R2-proven)
// ---------------------------------------------------------------------------
__global__ __launch_bounds__(256) void k_fill(float4* __restrict__ out) {
    int n   = blockIdx.x;
    int tid = threadIdx.x;

    int c0 = g_choice[n * 2 + 0];
    int c1 = g_choice[n * 2 + 1];
    int s0 = g_slot[n * 2 + 0];
    int s1 = g_slot[n * 2 + 1];
    int o0 = (s0 >= 0) ? c0 * CAP + s0 : -1;
    int o1 = (s1 >= 0) ? c1 * CAP + s1 : -1;

    float4* row = out + (size_t)n * (N_EXP * CAP / 4);

    #pragma unroll
    for (int q = 0; q < 4; q++) {
        int g = q * 256 + tid;
        int f = g * 4;
        float4 v;
        v.x = (o0 == f     || o1 == f    ) ? 1.0f : 0.0f;
        v.y = (o0 == f + 1 || o1 == f + 1) ? 1.0f : 0.0f;
        v.z = (o0 == f + 2 || o1 == f + 2) ? 1.0f : 0.0f;
        v.w = (o0 == f + 3 || o1 == f + 3) ? 1.0f : 0.0f;
        row[g] = v;
    }
}

// ---------------------------------------------------------------------------
extern "C" void kernel_launch(void* const* d_in, const int* in_sizes, int n_in,
                              void* d_out, int out_size) {
    const float* x = (const float*)d_in[0];   // [4096, 2048]
    const float* W = (const float*)d_in[1];   // [2048, 8]
    float* out = (float*)d_out;

    cudaFuncSetAttribute(k_logits_topk,
                         cudaFuncAttributeMaxDynamicSharedMemorySize, DYN_SMEM);

    k_logits_topk<<<GRID1, BLK1, DYN_SMEM>>>(x, W, out);
    k_scan<<<16, 1024>>>();
    k_fill<<<N_TOK, 256>>>((float4*)out);
}